// round 17
// baseline (speedup 1.0000x reference)
#include <cuda_runtime.h>
#include <cuda_bf16.h>
#include <cuda_fp16.h>

// MX quantize-dequantize: block size 32, E8M0 shared scale, E4M3 elements.
// v10 (resubmit; R15 was an infra failure): HW E4M3 cvt quantizer +
// MLP_p1=4 with the CLEAN interleaved lane mapping (the untested matrix
// cell: R5's MLP4 failure used the defective stride-2 pattern). Warp
// window = 128 consecutive float4 (2KB); lane l loads base+l, +32+l,
// +64+l, +96+l — four fully contiguous 512B LDG.128 per thread, nL=4
// each. Four independent 8-lane shfl amax reductions, interleaved.
// Exact pow2 bit-constructed scale math.

__device__ __forceinline__ void scales_from_amax(float m, float& scale, float& inv_scale) {
    // shared_exp = floor(log2(amax)) - 8, exact via exponent-field extract;
    // clamp keeps the bit-constructed pow2 floats normal. amax==0 -> all
    // elements are zero -> scale value irrelevant.
    int se = ((int)(__float_as_uint(m) >> 23) - 127) - 8;
    se = max(se, -126);
    scale     = __uint_as_float((unsigned)(se + 127) << 23);
    inv_scale = __uint_as_float((unsigned)(127 - se) << 23);
}

__device__ __forceinline__ float amax4(const float4& a) {
    return fmaxf(fmaxf(fabsf(a.x), fabsf(a.y)), fmaxf(fabsf(a.z), fabsf(a.w)));
}

// Quantize-dequantize two elements via the HW E4M3 converter.
__device__ __forceinline__ float2 qdq2_hw(float lo, float hi, float scale) {
    unsigned short e4m3x2;
    // RN-even, satfinite at 448, emin-shared subnormals == reference semantics
    asm("cvt.rn.satfinite.e4m3x2.f32 %0, %1, %2;"
        : "=h"(e4m3x2) : "f"(hi), "f"(lo));
    unsigned h2bits;
    asm("cvt.rn.f16x2.e4m3x2 %0, %1;" : "=r"(h2bits) : "h"(e4m3x2)); // exact
    __half2 h2 = *reinterpret_cast<__half2*>(&h2bits);
    float2 f = __half22float2(h2);
    f.x *= scale;   // exact pow2 multiply
    f.y *= scale;
    return f;
}

__device__ __forceinline__ float4 qdq4(const float4& a, float inv_scale, float scale) {
    float2 p0 = qdq2_hw(a.x * inv_scale, a.y * inv_scale, scale);
    float2 p1 = qdq2_hw(a.z * inv_scale, a.w * inv_scale, scale);
    float4 o;
    o.x = p0.x; o.y = p0.y; o.z = p1.x; o.w = p1.y;
    return o;
}

__global__ void __launch_bounds__(256)
mx_qdq_kernel(const float4* __restrict__ x, float4* __restrict__ y, int nvec) {
    int t    = blockIdx.x * blockDim.x + threadIdx.x;
    int lane = t & 31;
    int warp = t >> 5;
    int base = warp * 128;         // warp window: 128 consecutive float4 (2KB)
    int i0 = base + lane;          // four contiguous 512B warp accesses
    int i1 = i0 + 32;
    int i2 = i0 + 64;
    int i3 = i0 + 96;

    if (i3 >= nvec) {
        for (int i = i0; i < nvec; i += 32) {
            float4 a = x[i];
            float m = amax4(a);
            m = fmaxf(m, __shfl_xor_sync(0xffffffffu, m, 1));
            m = fmaxf(m, __shfl_xor_sync(0xffffffffu, m, 2));
            m = fmaxf(m, __shfl_xor_sync(0xffffffffu, m, 4));
            float s, is; scales_from_amax(m, s, is);
            y[i] = qdq4(a, is, s);
        }
        return;
    }

    // Front-batch all four loads: MLP_p1 = 4, all contiguous 512B accesses
    float4 a = x[i0];
    float4 b = x[i1];
    float4 c = x[i2];
    float4 d = x[i3];

    float mA = amax4(a);
    float mB = amax4(b);
    float mC = amax4(c);
    float mD = amax4(d);

    // Four independent 8-lane reductions (lanes 8k..8k+7 share one MX block
    // per load), interleaved so SHFL latency overlaps.
    float tA = __shfl_xor_sync(0xffffffffu, mA, 1);
    float tB = __shfl_xor_sync(0xffffffffu, mB, 1);
    float tC = __shfl_xor_sync(0xffffffffu, mC, 1);
    float tD = __shfl_xor_sync(0xffffffffu, mD, 1);
    mA = fmaxf(mA, tA); mB = fmaxf(mB, tB);
    mC = fmaxf(mC, tC); mD = fmaxf(mD, tD);
    tA = __shfl_xor_sync(0xffffffffu, mA, 2);
    tB = __shfl_xor_sync(0xffffffffu, mB, 2);
    tC = __shfl_xor_sync(0xffffffffu, mC, 2);
    tD = __shfl_xor_sync(0xffffffffu, mD, 2);
    mA = fmaxf(mA, tA); mB = fmaxf(mB, tB);
    mC = fmaxf(mC, tC); mD = fmaxf(mD, tD);
    tA = __shfl_xor_sync(0xffffffffu, mA, 4);
    tB = __shfl_xor_sync(0xffffffffu, mB, 4);
    tC = __shfl_xor_sync(0xffffffffu, mC, 4);
    tD = __shfl_xor_sync(0xffffffffu, mD, 4);
    mA = fmaxf(mA, tA); mB = fmaxf(mB, tB);
    mC = fmaxf(mC, tC); mD = fmaxf(mD, tD);

    float sA, isA, sB, isB, sC, isC, sD, isD;
    scales_from_amax(mA, sA, isA);
    scales_from_amax(mB, sB, isB);
    scales_from_amax(mC, sC, isC);
    scales_from_amax(mD, sD, isD);

    y[i0] = qdq4(a, isA, sA);
    y[i1] = qdq4(b, isB, sB);
    y[i2] = qdq4(c, isC, sC);
    y[i3] = qdq4(d, isD, sD);
}

extern "C" void kernel_launch(void* const* d_in, const int* in_sizes, int n_in,
                              void* d_out, int out_size) {
    const float* x = (const float*)d_in[0];
    float*       y = (float*)d_out;
    int n    = in_sizes[0];        // 33,554,432 (divisible by 32)
    int nvec = n / 4;              // 8,388,608 float4
    int nthreads = nvec / 4;       // 16 elements per thread
    int block = 256;
    int grid  = (nthreads + block - 1) / block;  // 8192
    mx_qdq_kernel<<<grid, block>>>((const float4*)x, (float4*)y, nvec);
}